// round 13
// baseline (speedup 1.0000x reference)
#include <cuda_runtime.h>
#include <cuda_bf16.h>
#include <cstdint>

// DANet spatial attention — all-bf16 mma.sync(m16n8k16).
// proj_v / out: 256x128 CTA tile, 8 warps (4x2), warp tile 64x64, 1 CTA/SM.
// proj_qk / scores: 128x128 CTA tile, 8 warps (2x4), warp tile 64x32.
// k-chunk 32, 3-stage single-sync cp.async pipeline. Softmax-free.

#define NB 16
#define NC 512
#define NHW 2304
#define ND 64
#define NMT 18

__device__ __nv_bfloat16 g_Xt [(size_t)NB * NHW * NC];
__device__ __nv_bfloat16 g_Wqk[(size_t)128 * NC];
__device__ __nv_bfloat16 g_Wv [(size_t)NC * NC];
__device__ __nv_bfloat16 g_Qt [(size_t)NB * NHW * ND];
__device__ __nv_bfloat16 g_Kt [(size_t)NB * NHW * ND];
__device__ __nv_bfloat16 g_Vb [(size_t)NB * NC * NHW];
__device__ __nv_bfloat16 g_Eb [(size_t)NB * NHW * NHW];
__device__ float g_psum[(size_t)NB * NMT * NHW];
__device__ float g_inv [(size_t)NB * NHW];

// ---------------------------------------------------------------------------
__device__ __forceinline__ void mma_bf16(float c[4],
                                         unsigned a0, unsigned a1, unsigned a2, unsigned a3,
                                         unsigned b0, unsigned b1) {
    asm volatile(
        "mma.sync.aligned.m16n8k16.row.col.f32.bf16.bf16.f32 "
        "{%0,%1,%2,%3}, {%4,%5,%6,%7}, {%8,%9}, {%0,%1,%2,%3};"
        : "+f"(c[0]), "+f"(c[1]), "+f"(c[2]), "+f"(c[3])
        : "r"(a0), "r"(a1), "r"(a2), "r"(a3), "r"(b0), "r"(b1));
}
__device__ __forceinline__ void ldsm_x4(unsigned r[4], uint32_t addr) {
    asm volatile("ldmatrix.sync.aligned.m8n8.x4.shared.b16 {%0,%1,%2,%3}, [%4];"
        : "=r"(r[0]), "=r"(r[1]), "=r"(r[2]), "=r"(r[3]) : "r"(addr));
}
#define CPA16(dst, src) asm volatile("cp.async.ca.shared.global [%0], [%1], 16;\n" :: "r"(dst), "l"(src))
#define CP_COMMIT()     asm volatile("cp.async.commit_group;\n")
#define CP_WAIT1()      asm volatile("cp.async.wait_group 1;\n")
#define CP_WAIT0()      asm volatile("cp.async.wait_group 0;\n")

#define SB32 40
#define SB64 72
#define TILE32 (128 * SB32)          // 128-row k32 tile elems
#define TILE32B (256 * SB32)         // 256-row k32 tile elems
#define STG_BYTES (TILE32 * 2)       // 10240 B

// ---------------------------------------------------------------------------
__global__ void __launch_bounds__(256)
convert_x(const float* __restrict__ X, __nv_bfloat16* __restrict__ Xt) {
    __shared__ float t[32][33];
    const int b  = blockIdx.z;
    const int n0 = blockIdx.x * 32;
    const int c0 = blockIdx.y * 32;
    const int tx = threadIdx.x & 31, ty = threadIdx.x >> 5;
    const float* Xb = X + (size_t)b * NC * NHW;
    __nv_bfloat16* Tb = Xt + (size_t)b * NHW * NC;
    #pragma unroll
    for (int k = 0; k < 4; k++)
        t[ty + k * 8][tx] = Xb[(size_t)(c0 + ty + k * 8) * NHW + n0 + tx];
    __syncthreads();
    #pragma unroll
    for (int k = 0; k < 4; k++)
        Tb[(size_t)(n0 + ty + k * 8) * NC + c0 + tx] = __float2bfloat16(t[tx][ty + k * 8]);
}

__global__ void __launch_bounds__(256)
convert_w(const float* __restrict__ Wq, const float* __restrict__ Wk,
          const float* __restrict__ Wv,
          __nv_bfloat16* __restrict__ Wqk, __nv_bfloat16* __restrict__ Wvb) {
    int idx = blockIdx.x * 256 + threadIdx.x;
    const int NQK = 128 * NC;
    if (idx < NQK) {
        int row = idx >> 9, col = idx & 511;
        float v = (row < 64) ? Wq[row * NC + col] : Wk[(row - 64) * NC + col];
        Wqk[idx] = __float2bfloat16(v);
    }
    int j = idx - NQK;
    if (j >= 0 && j < NC * NC)
        Wvb[j] = __float2bfloat16(Wv[j]);
}

// ---------------------------------------------------------------------------
// QK projection (128 rows): 128x128 tile, warp tile 64x32, transposed stores.
// ---------------------------------------------------------------------------
__global__ void __launch_bounds__(256, 2)
proj_qk(const __nv_bfloat16* __restrict__ Xt, const __nv_bfloat16* __restrict__ W,
        const float* __restrict__ B1, const float* __restrict__ B2,
        __nv_bfloat16* __restrict__ Qt, __nv_bfloat16* __restrict__ Kt) {
    extern __shared__ __align__(16) __nv_bfloat16 dsm[];
    __nv_bfloat16* sW = dsm;
    __nv_bfloat16* sX = dsm + 3 * TILE32;

    const int b  = blockIdx.z;
    const int n0 = blockIdx.x * 128;
    const __nv_bfloat16* Xb = Xt + (size_t)b * NHW * NC;

    const int tid = threadIdx.x;
    const int lane = tid & 31, wid = tid >> 5;
    const int wm = (wid >> 2) * 64, wn = (wid & 3) * 32;
    const int lr = lane >> 2, lc = lane & 3;
    const int lt = lane >> 3, l8 = lane & 7;
    const int aro = ((lt & 1) << 3) + l8, ako = (lt >> 1) << 3;
    const int bro = ((lt >> 1) << 3) + l8, bko = (lt & 1) << 3;

    const unsigned sWu = (unsigned)__cvta_generic_to_shared(sW);
    const unsigned sXu = (unsigned)__cvta_generic_to_shared(sX);
    const int lrow = tid >> 1, lc8 = (tid & 1) * 2;

    float acc[4][4][4];
    #pragma unroll
    for (int i = 0; i < 4; i++)
        #pragma unroll
        for (int j = 0; j < 4; j++)
            #pragma unroll
            for (int q = 0; q < 4; q++) acc[i][j][q] = 0.f;

    const int NCH = NC / 32;
    #define PLOAD(ch, stg) {                                                          \
        int mm = (ch) * 32;                                                           \
        _Pragma("unroll")                                                             \
        for (int p = 0; p < 2; p++) {                                                 \
            CPA16(sWu + ((stg) * TILE32 + lrow * SB32 + (lc8 + p) * 8) * 2,           \
                  W  + (size_t)lrow * NC + mm + (lc8 + p) * 8);                       \
            CPA16(sXu + ((stg) * TILE32 + lrow * SB32 + (lc8 + p) * 8) * 2,           \
                  Xb + (size_t)(n0 + lrow) * NC + mm + (lc8 + p) * 8);                \
        }                                                                             \
        CP_COMMIT();                                                                  \
    }

    PLOAD(0, 0); PLOAD(1, 1);
    #pragma unroll 1
    for (int ch = 0; ch < NCH; ch++) {
        int stg = ch % 3;
        if (ch + 1 < NCH) { CP_WAIT1(); } else { CP_WAIT0(); }
        __syncthreads();
        if (ch + 2 < NCH) PLOAD(ch + 2, (ch + 2) % 3);
        unsigned aB = sWu + (unsigned)(stg * TILE32) * 2;
        unsigned bB = sXu + (unsigned)(stg * TILE32) * 2;
        #pragma unroll
        for (int ks = 0; ks < 2; ks++) {
            const int kb = ks * 16;
            unsigned a[4][4], rb[2][4];
            #pragma unroll
            for (int i = 0; i < 4; i++)
                ldsm_x4(a[i], aB + ((wm + i * 16 + aro) * SB32 + kb + ako) * 2);
            #pragma unroll
            for (int j = 0; j < 2; j++)
                ldsm_x4(rb[j], bB + ((wn + j * 16 + bro) * SB32 + kb + bko) * 2);
            #pragma unroll
            for (int i = 0; i < 4; i++)
                #pragma unroll
                for (int j = 0; j < 4; j++)
                    mma_bf16(acc[i][j], a[i][0], a[i][1], a[i][2], a[i][3],
                             rb[j >> 1][(j & 1) * 2], rb[j >> 1][(j & 1) * 2 + 1]);
        }
    }

    __nv_bfloat16* Qb = Qt + (size_t)b * NHW * ND;
    __nv_bfloat16* Kb = Kt + (size_t)b * NHW * ND;
    #pragma unroll
    for (int i = 0; i < 4; i++) {
        int r0 = wm + i * 16 + lr;
        int r1 = r0 + 8;
        float bo0 = (r0 < 64 ? B1[r0] : B2[r0 - 64]);
        float bo1 = (r1 < 64 ? B1[r1] : B2[r1 - 64]);
        __nv_bfloat16* P0 = (r0 < 64 ? Qb : Kb);
        __nv_bfloat16* P1 = (r1 < 64 ? Qb : Kb);
        int rr0 = (r0 < 64 ? r0 : r0 - 64);
        int rr1 = (r1 < 64 ? r1 : r1 - 64);
        #pragma unroll
        for (int j = 0; j < 4; j++) {
            int col = n0 + wn + j * 8 + lc * 2;
            P0[(size_t)col * ND + rr0]       = __float2bfloat16(acc[i][j][0] + bo0);
            P0[(size_t)(col + 1) * ND + rr0] = __float2bfloat16(acc[i][j][1] + bo0);
            P1[(size_t)col * ND + rr1]       = __float2bfloat16(acc[i][j][2] + bo1);
            P1[(size_t)(col + 1) * ND + rr1] = __float2bfloat16(acc[i][j][3] + bo1);
        }
    }
    #undef PLOAD
}

// ---------------------------------------------------------------------------
// V projection: 256x128 tile, 8 warps (4x2), warp tile 64x64.
// smem per stage: A 256xSB32, B 128xSB32.
// ---------------------------------------------------------------------------
__global__ void __launch_bounds__(256, 1)
proj_v(const __nv_bfloat16* __restrict__ Xt, const __nv_bfloat16* __restrict__ W,
       const float* __restrict__ BV, __nv_bfloat16* __restrict__ Pv) {
    extern __shared__ __align__(16) __nv_bfloat16 dsm[];
    __nv_bfloat16* sW = dsm;                        // 3 stages x TILE32B
    __nv_bfloat16* sX = dsm + 3 * TILE32B;          // 3 stages x TILE32

    const int b  = blockIdx.z;
    const int n0 = blockIdx.x * 128;
    const int o0 = blockIdx.y * 256;
    const __nv_bfloat16* Xb = Xt + (size_t)b * NHW * NC;

    const int tid = threadIdx.x;
    const int lane = tid & 31, wid = tid >> 5;
    const int wm = (wid >> 1) * 64, wn = (wid & 1) * 64;
    const int lr = lane >> 2, lc = lane & 3;
    const int lt = lane >> 3, l8 = lane & 7;
    const int aro = ((lt & 1) << 3) + l8, ako = (lt >> 1) << 3;
    const int bro = ((lt >> 1) << 3) + l8, bko = (lt & 1) << 3;

    const unsigned sWu = (unsigned)__cvta_generic_to_shared(sW);
    const unsigned sXu = (unsigned)__cvta_generic_to_shared(sX);
    const int lrow = tid >> 1, lc8 = (tid & 1) * 2;   // B loader map

    float acc[4][8][4];
    #pragma unroll
    for (int i = 0; i < 4; i++)
        #pragma unroll
        for (int j = 0; j < 8; j++)
            #pragma unroll
            for (int q = 0; q < 4; q++) acc[i][j][q] = 0.f;

    const int NCH = NC / 32;
    #define PLOAD(ch, stg) {                                                          \
        int mm = (ch) * 32;                                                           \
        _Pragma("unroll")                                                             \
        for (int p = 0; p < 4; p++)                                                   \
            CPA16(sWu + ((stg) * TILE32B + tid * SB32 + p * 8) * 2,                   \
                  W + (size_t)(o0 + tid) * NC + mm + p * 8);                          \
        _Pragma("unroll")                                                             \
        for (int p = 0; p < 2; p++)                                                   \
            CPA16(sXu + ((stg) * TILE32 + lrow * SB32 + (lc8 + p) * 8) * 2,           \
                  Xb + (size_t)(n0 + lrow) * NC + mm + (lc8 + p) * 8);                \
        CP_COMMIT();                                                                  \
    }

    PLOAD(0, 0); PLOAD(1, 1);
    #pragma unroll 1
    for (int ch = 0; ch < NCH; ch++) {
        int stg = ch % 3;
        if (ch + 1 < NCH) { CP_WAIT1(); } else { CP_WAIT0(); }
        __syncthreads();
        if (ch + 2 < NCH) PLOAD(ch + 2, (ch + 2) % 3);
        unsigned aB = sWu + (unsigned)(stg * TILE32B) * 2;
        unsigned bB = sXu + (unsigned)(stg * TILE32) * 2;
        #pragma unroll
        for (int ks = 0; ks < 2; ks++) {
            const int kb = ks * 16;
            unsigned a[4][4], rb[4][4];
            #pragma unroll
            for (int i = 0; i < 4; i++)
                ldsm_x4(a[i], aB + ((wm + i * 16 + aro) * SB32 + kb + ako) * 2);
            #pragma unroll
            for (int j = 0; j < 4; j++)
                ldsm_x4(rb[j], bB + ((wn + j * 16 + bro) * SB32 + kb + bko) * 2);
            #pragma unroll
            for (int i = 0; i < 4; i++)
                #pragma unroll
                for (int jj = 0; jj < 8; jj++)
                    mma_bf16(acc[i][jj], a[i][0], a[i][1], a[i][2], a[i][3],
                             rb[jj >> 1][(jj & 1) * 2], rb[jj >> 1][(jj & 1) * 2 + 1]);
        }
    }

    __nv_bfloat16* Pb = Pv + (size_t)b * NC * NHW;
    #pragma unroll
    for (int i = 0; i < 4; i++) {
        int r0 = o0 + wm + i * 16 + lr;
        int r1 = r0 + 8;
        float bo0 = BV[r0];
        float bo1 = BV[r1];
        #pragma unroll
        for (int j = 0; j < 8; j++) {
            int col = n0 + wn + j * 8 + lc * 2;
            __nv_bfloat162 v0 = __floats2bfloat162_rn(acc[i][j][0] + bo0, acc[i][j][1] + bo0);
            __nv_bfloat162 v1 = __floats2bfloat162_rn(acc[i][j][2] + bo1, acc[i][j][3] + bo1);
            *(__nv_bfloat162*)&Pb[(size_t)r0 * NHW + col] = v0;
            *(__nv_bfloat162*)&Pb[(size_t)r1 * NHW + col] = v1;
        }
    }
    #undef PLOAD
}

// ---------------------------------------------------------------------------
// Scores+exp (unchanged): 128x128, 8 warps (2x4), single k=64 pass.
// ---------------------------------------------------------------------------
__global__ void __launch_bounds__(256, 2)
scores_bf16(const __nv_bfloat16* __restrict__ Qt, const __nv_bfloat16* __restrict__ Kt,
            __nv_bfloat16* __restrict__ E, float* __restrict__ psum) {
    const int b  = blockIdx.z;
    const int mt = blockIdx.x;
    const int m0 = mt * 128;
    const int n0 = blockIdx.y * 128;
    const __nv_bfloat16* Qb = Qt + (size_t)b * NHW * ND;
    const __nv_bfloat16* Kb = Kt + (size_t)b * NHW * ND;
    __nv_bfloat16*       Eb = E + (size_t)b * NHW * NHW;

    __shared__ __align__(16) __nv_bfloat16 sQ[128 * SB64];
    __shared__ __align__(16) __nv_bfloat16 sK[128 * SB64];
    __shared__ float sred[4][128];

    const int tid = threadIdx.x;
    const int lane = tid & 31, wid = tid >> 5;
    const int wm = (wid >> 2) * 64, wn = (wid & 3) * 32;
    const int lr = lane >> 2, lc = lane & 3;
    const int lt = lane >> 3, l8 = lane & 7;
    const int aro = ((lt & 1) << 3) + l8, ako = (lt >> 1) << 3;
    const int bro = ((lt >> 1) << 3) + l8, bko = (lt & 1) << 3;

    const unsigned sQu = (unsigned)__cvta_generic_to_shared(&sQ[0]);
    const unsigned sKu = (unsigned)__cvta_generic_to_shared(&sK[0]);

    #pragma unroll
    for (int p = 0; p < 4; p++) {
        int idx = tid + p * 256;
        int row = idx >> 3, c = idx & 7;
        CPA16(sQu + (row * SB64 + c * 8) * 2, Qb + (size_t)(n0 + row) * ND + c * 8);
        CPA16(sKu + (row * SB64 + c * 8) * 2, Kb + (size_t)(m0 + row) * ND + c * 8);
    }
    CP_COMMIT();

    float acc[4][4][4];
    #pragma unroll
    for (int i = 0; i < 4; i++)
        #pragma unroll
        for (int j = 0; j < 4; j++)
            #pragma unroll
            for (int q = 0; q < 4; q++) acc[i][j][q] = 0.f;

    CP_WAIT0();
    __syncthreads();

    #pragma unroll
    for (int t4 = 0; t4 < 4; t4++) {
        const int kb = t4 * 16;
        unsigned a[4][4], rb[2][4];
        #pragma unroll
        for (int i = 0; i < 4; i++)
            ldsm_x4(a[i], sQu + ((wm + i * 16 + aro) * SB64 + kb + ako) * 2);
        #pragma unroll
        for (int j = 0; j < 2; j++)
            ldsm_x4(rb[j], sKu + ((wn + j * 16 + bro) * SB64 + kb + bko) * 2);
        #pragma unroll
        for (int i = 0; i < 4; i++)
            #pragma unroll
            for (int j = 0; j < 4; j++)
                mma_bf16(acc[i][j], a[i][0], a[i][1], a[i][2], a[i][3],
                         rb[j >> 1][(j & 1) * 2], rb[j >> 1][(j & 1) * 2 + 1]);
    }

    const int cw = wid & 3;
    #pragma unroll
    for (int i = 0; i < 4; i++) {
        int r0 = n0 + wm + i * 16 + lr;
        int r1 = r0 + 8;
        float s0 = 0.f, s1 = 0.f;
        #pragma unroll
        for (int j = 0; j < 4; j++) {
            int col = m0 + wn + j * 8 + lc * 2;
            __nv_bfloat162 h0 = __floats2bfloat162_rn(__expf(acc[i][j][0]), __expf(acc[i][j][1]));
            __nv_bfloat162 h1 = __floats2bfloat162_rn(__expf(acc[i][j][2]), __expf(acc[i][j][3]));
            *(__nv_bfloat162*)&Eb[(size_t)r0 * NHW + col] = h0;
            *(__nv_bfloat162*)&Eb[(size_t)r1 * NHW + col] = h1;
            float2 f0 = __bfloat1622float2(h0);
            float2 f1 = __bfloat1622float2(h1);
            s0 += f0.x + f0.y;
            s1 += f1.x + f1.y;
        }
        s0 += __shfl_xor_sync(0xffffffffu, s0, 1);
        s0 += __shfl_xor_sync(0xffffffffu, s0, 2);
        s1 += __shfl_xor_sync(0xffffffffu, s1, 1);
        s1 += __shfl_xor_sync(0xffffffffu, s1, 2);
        if (lc == 0) {
            sred[cw][wm + i * 16 + lr]     = s0;
            sred[cw][wm + i * 16 + lr + 8] = s1;
        }
    }
    __syncthreads();
    if (tid < 128) {
        float s = sred[0][tid] + sred[1][tid] + sred[2][tid] + sred[3][tid];
        psum[((size_t)(b * NMT + mt)) * NHW + n0 + tid] = s;
    }
}

// ---------------------------------------------------------------------------
__global__ void invsum_kernel(const float* __restrict__ psum, float* __restrict__ inv) {
    int idx = blockIdx.x * 256 + threadIdx.x;
    if (idx >= NB * NHW) return;
    int b = idx / NHW, n = idx - b * NHW;
    const float* ps = psum + (size_t)b * NMT * NHW + n;
    float s = 0.f;
    #pragma unroll
    for (int mt = 0; mt < NMT; mt++) s += ps[(size_t)mt * NHW];
    inv[idx] = 1.f / s;
}

// ---------------------------------------------------------------------------
// Out: 256(c)x128(n) tile, 8 warps (4x2), warp tile 64x64, NCH=72.
// ---------------------------------------------------------------------------
__global__ void __launch_bounds__(256, 1)
out_bf16(const __nv_bfloat16* __restrict__ V, const __nv_bfloat16* __restrict__ E,
         const float* __restrict__ inv, const float* __restrict__ X,
         const float* __restrict__ gamma, float* __restrict__ Y) {
    extern __shared__ __align__(16) __nv_bfloat16 dsm[];
    __nv_bfloat16* sV = dsm;                        // 3 x TILE32B
    __nv_bfloat16* sE = dsm + 3 * TILE32B;          // 3 x TILE32

    const int b  = blockIdx.z;
    const int c0 = blockIdx.x * 256;
    const int n0 = blockIdx.y * 128;
    const __nv_bfloat16* Vb = V + (size_t)b * NC * NHW;
    const __nv_bfloat16* Ab = E + (size_t)b * NHW * NHW;
    const float* Xb = X + (size_t)b * NC * NHW;
    const float* invb = inv + (size_t)b * NHW;
    float*       Yb = Y + (size_t)b * NC * NHW;

    const int tid = threadIdx.x;
    const int lane = tid & 31, wid = tid >> 5;
    const int wm = (wid >> 1) * 64, wn = (wid & 1) * 64;
    const int lr = lane >> 2, lc = lane & 3;
    const int lt = lane >> 3, l8 = lane & 7;
    const int aro = ((lt & 1) << 3) + l8, ako = (lt >> 1) << 3;
    const int bro = ((lt >> 1) << 3) + l8, bko = (lt & 1) << 3;

    const unsigned sVu = (unsigned)__cvta_generic_to_shared(sV);
    const unsigned sEu = (unsigned)__cvta_generic_to_shared(sE);
    const int lrow = tid >> 1, lc8 = (tid & 1) * 2;

    float acc[4][8][4];
    #pragma unroll
    for (int i = 0; i < 4; i++)
        #pragma unroll
        for (int j = 0; j < 8; j++)
            #pragma unroll
            for (int q = 0; q < 4; q++) acc[i][j][q] = 0.f;

    const int NCH = NHW / 32;   // 72
    #define OLOAD(ch, stg) {                                                          \
        int mm = (ch) * 32;                                                           \
        _Pragma("unroll")                                                             \
        for (int p = 0; p < 4; p++)                                                   \
            CPA16(sVu + ((stg) * TILE32B + tid * SB32 + p * 8) * 2,                   \
                  Vb + (size_t)(c0 + tid) * NHW + mm + p * 8);                        \
        _Pragma("unroll")                                                             \
        for (int p = 0; p < 2; p++)                                                   \
            CPA16(sEu + ((stg) * TILE32 + lrow * SB32 + (lc8 + p) * 8) * 2,           \
                  Ab + (size_t)(n0 + lrow) * NHW + mm + (lc8 + p) * 8);               \
        CP_COMMIT();                                                                  \
    }

    OLOAD(0, 0); OLOAD(1, 1);
    #pragma unroll 1
    for (int ch = 0; ch < NCH; ch++) {
        int stg = ch % 3;
        if (ch + 1 < NCH) { CP_WAIT1(); } else { CP_WAIT0(); }
        __syncthreads();
        if (ch + 2 < NCH) OLOAD(ch + 2, (ch + 2) % 3);
        unsigned aB = sVu + (unsigned)(stg * TILE32B) * 2;
        unsigned bB = sEu + (unsigned)(stg * TILE32) * 2;
        #pragma unroll
        for (int ks = 0; ks < 2; ks++) {
            const int kb = ks * 16;
            unsigned a[4][4], rb[4][4];
            #pragma unroll
            for (int i = 0; i < 4; i++)
                ldsm_x4(a[i], aB + ((wm + i * 16 + aro) * SB32 + kb + ako) * 2);
            #pragma unroll
            for (int j = 0; j < 4; j++)
                ldsm_x4(rb[j], bB + ((wn + j * 16 + bro) * SB32 + kb + bko) * 2);
            #pragma unroll
            for (int i = 0; i < 4; i++)
                #pragma unroll
                for (int jj = 0; jj < 8; jj++)
                    mma_bf16(acc[i][jj], a[i][0], a[i][1], a[i][2], a[i][3],
                             rb[jj >> 1][(jj & 1) * 2], rb[jj >> 1][(jj & 1) * 2 + 1]);
        }
    }

    const float g = gamma[0];
    #pragma unroll
    for (int i = 0; i < 4; i++) {
        int r0 = c0 + wm + i * 16 + lr;
        int r1 = r0 + 8;
        #pragma unroll
        for (int j = 0; j < 8; j++) {
            int col = n0 + wn + j * 8 + lc * 2;
            float2 iv = *(const float2*)&invb[col];
            size_t i0 = (size_t)r0 * NHW + col;
            size_t i1 = (size_t)r1 * NHW + col;
            float2 x0 = *(const float2*)&Xb[i0];
            float2 x1 = *(const float2*)&Xb[i1];
            float2 v0 = { g * acc[i][j][0] * iv.x + x0.x, g * acc[i][j][1] * iv.y + x0.y };
            float2 v1 = { g * acc[i][j][2] * iv.x + x1.x, g * acc[i][j][3] * iv.y + x1.y };
            *(float2*)&Yb[i0] = v0;
            *(float2*)&Yb[i1] = v1;
        }
    }
    #undef OLOAD
}

// ---------------------------------------------------------------------------
extern "C" void kernel_launch(void* const* d_in, const int* in_sizes, int n_in,
                              void* d_out, int out_size) {
    const float* X     = (const float*)d_in[0];
    const float* Wq    = (const float*)d_in[1];
    const float* bq    = (const float*)d_in[2];
    const float* Wk    = (const float*)d_in[3];
    const float* bk    = (const float*)d_in[4];
    const float* Wv    = (const float*)d_in[5];
    const float* bv    = (const float*)d_in[6];
    const float* gamma = (const float*)d_in[7];
    float* Y = (float*)d_out;

    __nv_bfloat16 *Xt, *Wqk, *Wvb, *Qt, *Kt, *Vb, *Eb;
    float *PS, *IV;
    cudaGetSymbolAddress((void**)&Xt,  g_Xt);
    cudaGetSymbolAddress((void**)&Wqk, g_Wqk);
    cudaGetSymbolAddress((void**)&Wvb, g_Wv);
    cudaGetSymbolAddress((void**)&Qt,  g_Qt);
    cudaGetSymbolAddress((void**)&Kt,  g_Kt);
    cudaGetSymbolAddress((void**)&Vb,  g_Vb);
    cudaGetSymbolAddress((void**)&Eb,  g_Eb);
    cudaGetSymbolAddress((void**)&PS,  g_psum);
    cudaGetSymbolAddress((void**)&IV,  g_inv);

    const int DSM_QK = 6 * STG_BYTES;                        // 61440 B
    const int DSM_BIG = 3 * (TILE32B + TILE32) * 2;          // 92160 B
    cudaFuncSetAttribute(proj_qk,  cudaFuncAttributeMaxDynamicSharedMemorySize, DSM_QK);
    cudaFuncSetAttribute(proj_v,   cudaFuncAttributeMaxDynamicSharedMemorySize, DSM_BIG);
    cudaFuncSetAttribute(out_bf16, cudaFuncAttributeMaxDynamicSharedMemorySize, DSM_BIG);

    convert_x<<<dim3(NHW / 32, NC / 32, NB), 256>>>(X, Xt);
    convert_w<<<(128 * NC + NC * NC + 255) / 256, 256>>>(Wq, Wk, Wv, Wqk, Wvb);
    proj_qk<<<dim3(NHW / 128, 1, NB), 256, DSM_QK>>>(Xt, Wqk, bq, bk, Qt, Kt);
    proj_v<<<dim3(NHW / 128, NC / 256, NB), 256, DSM_BIG>>>(Xt, Wvb, bv, Vb);
    scores_bf16<<<dim3(NMT, NMT, NB), 256>>>(Qt, Kt, Eb, PS);
    invsum_kernel<<<(NB * NHW + 255) / 256, 256>>>(PS, IV);
    out_bf16<<<dim3(NC / 256, NHW / 128, NB), 256, DSM_BIG>>>(Vb, Eb, IV, X, gamma, Y);
}

// round 14
// speedup vs baseline: 1.1308x; 1.1308x over previous
#include <cuda_runtime.h>
#include <cuda_bf16.h>
#include <cstdint>

// DANet spatial attention — all-bf16 mma.sync(m16n8k16), 8-warp CTAs,
// k-chunk 32, 3-stage single-sync cp.async pipeline (R11 config),
// fast 64x64 convert_x. B=16, C=512, HW=2304, d=64. Softmax-free.

#define NB 16
#define NC 512
#define NHW 2304
#define ND 64
#define NMT 18

__device__ __nv_bfloat16 g_Xt [(size_t)NB * NHW * NC];
__device__ __nv_bfloat16 g_Wqk[(size_t)128 * NC];
__device__ __nv_bfloat16 g_Wv [(size_t)NC * NC];
__device__ __nv_bfloat16 g_Qt [(size_t)NB * NHW * ND];
__device__ __nv_bfloat16 g_Kt [(size_t)NB * NHW * ND];
__device__ __nv_bfloat16 g_Vb [(size_t)NB * NC * NHW];
__device__ __nv_bfloat16 g_Eb [(size_t)NB * NHW * NHW];
__device__ float g_psum[(size_t)NB * NMT * NHW];
__device__ float g_inv [(size_t)NB * NHW];

// ---------------------------------------------------------------------------
__device__ __forceinline__ void mma_bf16(float c[4],
                                         unsigned a0, unsigned a1, unsigned a2, unsigned a3,
                                         unsigned b0, unsigned b1) {
    asm volatile(
        "mma.sync.aligned.m16n8k16.row.col.f32.bf16.bf16.f32 "
        "{%0,%1,%2,%3}, {%4,%5,%6,%7}, {%8,%9}, {%0,%1,%2,%3};"
        : "+f"(c[0]), "+f"(c[1]), "+f"(c[2]), "+f"(c[3])
        : "r"(a0), "r"(a1), "r"(a2), "r"(a3), "r"(b0), "r"(b1));
}
__device__ __forceinline__ void ldsm_x4(unsigned r[4], uint32_t addr) {
    asm volatile("ldmatrix.sync.aligned.m8n8.x4.shared.b16 {%0,%1,%2,%3}, [%4];"
        : "=r"(r[0]), "=r"(r[1]), "=r"(r[2]), "=r"(r[3]) : "r"(addr));
}
#define CPA16(dst, src) asm volatile("cp.async.ca.shared.global [%0], [%1], 16;\n" :: "r"(dst), "l"(src))
#define CP_COMMIT()     asm volatile("cp.async.commit_group;\n")
#define CP_WAIT1()      asm volatile("cp.async.wait_group 1;\n")
#define CP_WAIT0()      asm volatile("cp.async.wait_group 0;\n")

#define SB32 40
#define SB64 72
#define TILE32 (128 * SB32)
#define STG_BYTES (TILE32 * 2)       // 10240 B

// ---------------------------------------------------------------------------
// X [b][c][n] fp32 -> Xt [b][n][c] bf16.  64x64 tiles, float4 I/O.
// ---------------------------------------------------------------------------
__global__ void __launch_bounds__(256)
convert_x(const float* __restrict__ X, __nv_bfloat16* __restrict__ Xt) {
    __shared__ float t[64][65];
    const int b  = blockIdx.z;
    const int n0 = blockIdx.x * 64;
    const int c0 = blockIdx.y * 64;
    const int tx = threadIdx.x & 15, ty = threadIdx.x >> 4;   // 16 x 16
    const float* Xb = X + (size_t)b * NC * NHW;
    __nv_bfloat16* Tb = Xt + (size_t)b * NHW * NC;

    #pragma unroll
    for (int k = 0; k < 4; k++) {
        int row = ty + k * 16;   // c index
        float4 v = *(const float4*)&Xb[(size_t)(c0 + row) * NHW + n0 + tx * 4];
        t[row][tx * 4 + 0] = v.x;
        t[row][tx * 4 + 1] = v.y;
        t[row][tx * 4 + 2] = v.z;
        t[row][tx * 4 + 3] = v.w;
    }
    __syncthreads();
    #pragma unroll
    for (int k = 0; k < 4; k++) {
        int nrow = ty + k * 16;  // n index
        float v0 = t[tx * 4 + 0][nrow];
        float v1 = t[tx * 4 + 1][nrow];
        float v2 = t[tx * 4 + 2][nrow];
        float v3 = t[tx * 4 + 3][nrow];
        __nv_bfloat162 h0 = __floats2bfloat162_rn(v0, v1);
        __nv_bfloat162 h1 = __floats2bfloat162_rn(v2, v3);
        __nv_bfloat162* dst = (__nv_bfloat162*)&Tb[(size_t)(n0 + nrow) * NC + c0 + tx * 4];
        dst[0] = h0;
        dst[1] = h1;
    }
}

__global__ void __launch_bounds__(256)
convert_w(const float* __restrict__ Wq, const float* __restrict__ Wk,
          const float* __restrict__ Wv,
          __nv_bfloat16* __restrict__ Wqk, __nv_bfloat16* __restrict__ Wvb) {
    int idx = blockIdx.x * 256 + threadIdx.x;
    const int NQK = 128 * NC;
    if (idx < NQK) {
        int row = idx >> 9, col = idx & 511;
        float v = (row < 64) ? Wq[row * NC + col] : Wk[(row - 64) * NC + col];
        Wqk[idx] = __float2bfloat16(v);
    }
    int j = idx - NQK;
    if (j >= 0 && j < NC * NC)
        Wvb[j] = __float2bfloat16(Wv[j]);
}

// ---------------------------------------------------------------------------
// bf16 projection, 256 thr, 8 warps (2x4), warp tile 64x32, k-chunk 32,
// 3-stage single-sync pipeline.
// ---------------------------------------------------------------------------
template<bool QKT>
__global__ void __launch_bounds__(256, 2)
proj_bf16(const __nv_bfloat16* __restrict__ Xt, const __nv_bfloat16* __restrict__ W,
          const float* __restrict__ B1, const float* __restrict__ B2, int split,
          __nv_bfloat16* __restrict__ Pv,
          __nv_bfloat16* __restrict__ Qt, __nv_bfloat16* __restrict__ Kt) {
    extern __shared__ __align__(16) __nv_bfloat16 dsm[];
    __nv_bfloat16* sW = dsm;
    __nv_bfloat16* sX = dsm + 3 * TILE32;

    const int b  = blockIdx.z;
    const int n0 = blockIdx.x * 128;
    const int o0 = blockIdx.y * 128;
    const __nv_bfloat16* Xb = Xt + (size_t)b * NHW * NC;

    const int tid = threadIdx.x;
    const int lane = tid & 31, wid = tid >> 5;
    const int wm = (wid >> 2) * 64, wn = (wid & 3) * 32;
    const int lr = lane >> 2, lc = lane & 3;
    const int lt = lane >> 3, l8 = lane & 7;
    const int aro = ((lt & 1) << 3) + l8, ako = (lt >> 1) << 3;
    const int bro = ((lt >> 1) << 3) + l8, bko = (lt & 1) << 3;

    const unsigned sWu = (unsigned)__cvta_generic_to_shared(sW);
    const unsigned sXu = (unsigned)__cvta_generic_to_shared(sX);

    const int lrow = tid >> 1, lc8 = (tid & 1) * 2;

    float acc[4][4][4];
    #pragma unroll
    for (int i = 0; i < 4; i++)
        #pragma unroll
        for (int j = 0; j < 4; j++)
            #pragma unroll
            for (int q = 0; q < 4; q++) acc[i][j][q] = 0.f;

    const int NCH = NC / 32;   // 16
    #define PLOAD(ch, stg) {                                                          \
        int mm = (ch) * 32;                                                           \
        _Pragma("unroll")                                                             \
        for (int p = 0; p < 2; p++) {                                                 \
            CPA16(sWu + ((stg) * TILE32 + lrow * SB32 + (lc8 + p) * 8) * 2,           \
                  W  + (size_t)(o0 + lrow) * NC + mm + (lc8 + p) * 8);                \
            CPA16(sXu + ((stg) * TILE32 + lrow * SB32 + (lc8 + p) * 8) * 2,           \
                  Xb + (size_t)(n0 + lrow) * NC + mm + (lc8 + p) * 8);                \
        }                                                                             \
        CP_COMMIT();                                                                  \
    }

    PLOAD(0, 0); PLOAD(1, 1);
    #pragma unroll 1
    for (int ch = 0; ch < NCH; ch++) {
        int stg = ch % 3;
        if (ch + 1 < NCH) { CP_WAIT1(); } else { CP_WAIT0(); }
        __syncthreads();
        if (ch + 2 < NCH) PLOAD(ch + 2, (ch + 2) % 3);
        unsigned aB = sWu + (unsigned)(stg * TILE32) * 2;
        unsigned bB = sXu + (unsigned)(stg * TILE32) * 2;
        #pragma unroll
        for (int ks = 0; ks < 2; ks++) {
            const int kb = ks * 16;
            unsigned a[4][4], rb[2][4];
            #pragma unroll
            for (int i = 0; i < 4; i++)
                ldsm_x4(a[i], aB + ((wm + i * 16 + aro) * SB32 + kb + ako) * 2);
            #pragma unroll
            for (int j = 0; j < 2; j++)
                ldsm_x4(rb[j], bB + ((wn + j * 16 + bro) * SB32 + kb + bko) * 2);
            #pragma unroll
            for (int i = 0; i < 4; i++)
                #pragma unroll
                for (int j = 0; j < 4; j++)
                    mma_bf16(acc[i][j], a[i][0], a[i][1], a[i][2], a[i][3],
                             rb[j >> 1][(j & 1) * 2], rb[j >> 1][(j & 1) * 2 + 1]);
        }
    }

    if (QKT) {
        __nv_bfloat16* Qb = Qt + (size_t)b * NHW * ND;
        __nv_bfloat16* Kb = Kt + (size_t)b * NHW * ND;
        #pragma unroll
        for (int i = 0; i < 4; i++) {
            int r0 = o0 + wm + i * 16 + lr;
            int r1 = r0 + 8;
            float bo0 = (r0 < split ? B1[r0] : B2[r0 - split]);
            float bo1 = (r1 < split ? B1[r1] : B2[r1 - split]);
            __nv_bfloat16* P0 = (r0 < split ? Qb : Kb);
            __nv_bfloat16* P1 = (r1 < split ? Qb : Kb);
            int rr0 = (r0 < split ? r0 : r0 - split);
            int rr1 = (r1 < split ? r1 : r1 - split);
            #pragma unroll
            for (int j = 0; j < 4; j++) {
                int col = n0 + wn + j * 8 + lc * 2;
                P0[(size_t)col * ND + rr0]       = __float2bfloat16(acc[i][j][0] + bo0);
                P0[(size_t)(col + 1) * ND + rr0] = __float2bfloat16(acc[i][j][1] + bo0);
                P1[(size_t)col * ND + rr1]       = __float2bfloat16(acc[i][j][2] + bo1);
                P1[(size_t)(col + 1) * ND + rr1] = __float2bfloat16(acc[i][j][3] + bo1);
            }
        }
    } else {
        __nv_bfloat16* Pb = Pv + (size_t)b * NC * NHW;
        #pragma unroll
        for (int i = 0; i < 4; i++) {
            int r0 = o0 + wm + i * 16 + lr;
            int r1 = r0 + 8;
            float bo0 = B1[r0];
            float bo1 = B1[r1];
            #pragma unroll
            for (int j = 0; j < 4; j++) {
                int col = n0 + wn + j * 8 + lc * 2;
                __nv_bfloat162 v0 = __floats2bfloat162_rn(acc[i][j][0] + bo0, acc[i][j][1] + bo0);
                __nv_bfloat162 v1 = __floats2bfloat162_rn(acc[i][j][2] + bo1, acc[i][j][3] + bo1);
                *(__nv_bfloat162*)&Pb[(size_t)r0 * NHW + col] = v0;
                *(__nv_bfloat162*)&Pb[(size_t)r1 * NHW + col] = v1;
            }
        }
    }
    #undef PLOAD
}

// ---------------------------------------------------------------------------
// Scores+exp, 256 thr, 8 warps (2x4), warp tile 64x32, single k=64 pass.
// ---------------------------------------------------------------------------
__global__ void __launch_bounds__(256, 2)
scores_bf16(const __nv_bfloat16* __restrict__ Qt, const __nv_bfloat16* __restrict__ Kt,
            __nv_bfloat16* __restrict__ E, float* __restrict__ psum) {
    const int b  = blockIdx.z;
    const int mt = blockIdx.x;
    const int m0 = mt * 128;
    const int n0 = blockIdx.y * 128;
    const __nv_bfloat16* Qb = Qt + (size_t)b * NHW * ND;
    const __nv_bfloat16* Kb = Kt + (size_t)b * NHW * ND;
    __nv_bfloat16*       Eb = E + (size_t)b * NHW * NHW;

    __shared__ __align__(16) __nv_bfloat16 sQ[128 * SB64];
    __shared__ __align__(16) __nv_bfloat16 sK[128 * SB64];
    __shared__ float sred[4][128];

    const int tid = threadIdx.x;
    const int lane = tid & 31, wid = tid >> 5;
    const int wm = (wid >> 2) * 64, wn = (wid & 3) * 32;
    const int lr = lane >> 2, lc = lane & 3;
    const int lt = lane >> 3, l8 = lane & 7;
    const int aro = ((lt & 1) << 3) + l8, ako = (lt >> 1) << 3;
    const int bro = ((lt >> 1) << 3) + l8, bko = (lt & 1) << 3;

    const unsigned sQu = (unsigned)__cvta_generic_to_shared(&sQ[0]);
    const unsigned sKu = (unsigned)__cvta_generic_to_shared(&sK[0]);

    #pragma unroll
    for (int p = 0; p < 4; p++) {
        int idx = tid + p * 256;
        int row = idx >> 3, c = idx & 7;
        CPA16(sQu + (row * SB64 + c * 8) * 2, Qb + (size_t)(n0 + row) * ND + c * 8);
        CPA16(sKu + (row * SB64 + c * 8) * 2, Kb + (size_t)(m0 + row) * ND + c * 8);
    }
    CP_COMMIT();

    float acc[4][4][4];
    #pragma unroll
    for (int i = 0; i < 4; i++)
        #pragma unroll
        for (int j = 0; j < 4; j++)
            #pragma unroll
            for (int q = 0; q < 4; q++) acc[i][j][q] = 0.f;

    CP_WAIT0();
    __syncthreads();

    #pragma unroll
    for (int t4 = 0; t4 < 4; t4++) {
        const int kb = t4 * 16;
        unsigned a[4][4], rb[2][4];
        #pragma unroll
        for (int i = 0; i < 4; i++)
            ldsm_x4(a[i], sQu + ((wm + i * 16 + aro) * SB64 + kb + ako) * 2);
        #pragma unroll
        for (int j = 0; j < 2; j++)
            ldsm_x4(rb[j], sKu + ((wn + j * 16 + bro) * SB64 + kb + bko) * 2);
        #pragma unroll
        for (int i = 0; i < 4; i++)
            #pragma unroll
            for (int j = 0; j < 4; j++)
                mma_bf16(acc[i][j], a[i][0], a[i][1], a[i][2], a[i][3],
                         rb[j >> 1][(j & 1) * 2], rb[j >> 1][(j & 1) * 2 + 1]);
    }

    const int cw = wid & 3;
    #pragma unroll
    for (int i = 0; i < 4; i++) {
        int r0 = n0 + wm + i * 16 + lr;
        int r1 = r0 + 8;
        float s0 = 0.f, s1 = 0.f;
        #pragma unroll
        for (int j = 0; j < 4; j++) {
            int col = m0 + wn + j * 8 + lc * 2;
            __nv_bfloat162 h0 = __floats2bfloat162_rn(__expf(acc[i][j][0]), __expf(acc[i][j][1]));
            __nv_bfloat162 h1 = __floats2bfloat162_rn(__expf(acc[i][j][2]), __expf(acc[i][j][3]));
            *(__nv_bfloat162*)&Eb[(size_t)r0 * NHW + col] = h0;
            *(__nv_bfloat162*)&Eb[(size_t)r1 * NHW + col] = h1;
            float2 f0 = __bfloat1622float2(h0);
            float2 f1 = __bfloat1622float2(h1);
            s0 += f0.x + f0.y;
            s1 += f1.x + f1.y;
        }
        s0 += __shfl_xor_sync(0xffffffffu, s0, 1);
        s0 += __shfl_xor_sync(0xffffffffu, s0, 2);
        s1 += __shfl_xor_sync(0xffffffffu, s1, 1);
        s1 += __shfl_xor_sync(0xffffffffu, s1, 2);
        if (lc == 0) {
            sred[cw][wm + i * 16 + lr]     = s0;
            sred[cw][wm + i * 16 + lr + 8] = s1;
        }
    }
    __syncthreads();
    if (tid < 128) {
        float s = sred[0][tid] + sred[1][tid] + sred[2][tid] + sred[3][tid];
        psum[((size_t)(b * NMT + mt)) * NHW + n0 + tid] = s;
    }
}

// ---------------------------------------------------------------------------
__global__ void invsum_kernel(const float* __restrict__ psum, float* __restrict__ inv) {
    int idx = blockIdx.x * 256 + threadIdx.x;
    if (idx >= NB * NHW) return;
    int b = idx / NHW, n = idx - b * NHW;
    const float* ps = psum + (size_t)b * NMT * NHW + n;
    float s = 0.f;
    #pragma unroll
    for (int mt = 0; mt < NMT; mt++) s += ps[(size_t)mt * NHW];
    inv[idx] = 1.f / s;
}

// ---------------------------------------------------------------------------
// Out, 256 thr, 8 warps (2x4), warp tile 64x32, k-chunk 32, 3-stage
// single-sync pipeline, NCH=72.
// ---------------------------------------------------------------------------
__global__ void __launch_bounds__(256, 2)
out_bf16(const __nv_bfloat16* __restrict__ V, const __nv_bfloat16* __restrict__ E,
         const float* __restrict__ inv, const float* __restrict__ X,
         const float* __restrict__ gamma, float* __restrict__ Y) {
    extern __shared__ __align__(16) __nv_bfloat16 dsm[];
    __nv_bfloat16* sV = dsm;
    __nv_bfloat16* sE = dsm + 3 * TILE32;

    const int b  = blockIdx.z;
    const int c0 = blockIdx.x * 128;
    const int n0 = blockIdx.y * 128;
    const __nv_bfloat16* Vb = V + (size_t)b * NC * NHW;
    const __nv_bfloat16* Ab = E + (size_t)b * NHW * NHW;
    const float* Xb = X + (size_t)b * NC * NHW;
    const float* invb = inv + (size_t)b * NHW;
    float*       Yb = Y + (size_t)b * NC * NHW;

    const int tid = threadIdx.x;
    const int lane = tid & 31, wid = tid >> 5;
    const int wm = (wid >> 2) * 64, wn = (wid & 3) * 32;
    const int lr = lane >> 2, lc = lane & 3;
    const int lt = lane >> 3, l8 = lane & 7;
    const int aro = ((lt & 1) << 3) + l8, ako = (lt >> 1) << 3;
    const int bro = ((lt >> 1) << 3) + l8, bko = (lt & 1) << 3;

    const unsigned sVu = (unsigned)__cvta_generic_to_shared(sV);
    const unsigned sEu = (unsigned)__cvta_generic_to_shared(sE);

    const int lrow = tid >> 1, lc8 = (tid & 1) * 2;

    float acc[4][4][4];
    #pragma unroll
    for (int i = 0; i < 4; i++)
        #pragma unroll
        for (int j = 0; j < 4; j++)
            #pragma unroll
            for (int q = 0; q < 4; q++) acc[i][j][q] = 0.f;

    const int NCH = NHW / 32;   // 72
    #define OLOAD(ch, stg) {                                                          \
        int mm = (ch) * 32;                                                           \
        _Pragma("unroll")                                                             \
        for (int p = 0; p < 2; p++) {                                                 \
            CPA16(sVu + ((stg) * TILE32 + lrow * SB32 + (lc8 + p) * 8) * 2,           \
                  Vb + (size_t)(c0 + lrow) * NHW + mm + (lc8 + p) * 8);               \
            CPA16(sEu + ((stg) * TILE32 + lrow * SB32 + (lc8 + p) * 8) * 2,           \
                  Ab + (size_t)(n0 + lrow) * NHW + mm + (lc8 + p) * 8);               \
        }                                                                             \
        CP_COMMIT();                                                                  \
    }

    OLOAD(0, 0); OLOAD(1, 1);
    #pragma unroll 1
    for (int ch = 0; ch < NCH; ch++) {
        int stg = ch % 3;
        if (ch + 1 < NCH) { CP_WAIT1(); } else { CP_WAIT0(); }
        __syncthreads();
        if (ch + 2 < NCH) OLOAD(ch + 2, (ch + 2) % 3);
        unsigned aB = sVu + (unsigned)(stg * TILE32) * 2;
        unsigned bB = sEu + (unsigned)(stg * TILE32) * 2;
        #pragma unroll
        for (int ks = 0; ks < 2; ks++) {
            const int kb = ks * 16;
            unsigned a[4][4], rb[2][4];
            #pragma unroll
            for (int i = 0; i < 4; i++)
                ldsm_x4(a[i], aB + ((wm + i * 16 + aro) * SB32 + kb + ako) * 2);
            #pragma unroll
            for (int j = 0; j < 2; j++)
                ldsm_x4(rb[j], bB + ((wn + j * 16 + bro) * SB32 + kb + bko) * 2);
            #pragma unroll
            for (int i = 0; i < 4; i++)
                #pragma unroll
                for (int j = 0; j < 4; j++)
                    mma_bf16(acc[i][j], a[i][0], a[i][1], a[i][2], a[i][3],
                             rb[j >> 1][(j & 1) * 2], rb[j >> 1][(j & 1) * 2 + 1]);
        }
    }

    const float g = gamma[0];
    #pragma unroll
    for (int i = 0; i < 4; i++) {
        int r0 = c0 + wm + i * 16 + lr;
        int r1 = r0 + 8;
        #pragma unroll
        for (int j = 0; j < 4; j++) {
            int col = n0 + wn + j * 8 + lc * 2;
            float2 iv = *(const float2*)&invb[col];
            size_t i0 = (size_t)r0 * NHW + col;
            size_t i1 = (size_t)r1 * NHW + col;
            float2 x0 = *(const float2*)&Xb[i0];
            float2 x1 = *(const float2*)&Xb[i1];
            float2 v0 = { g * acc[i][j][0] * iv.x + x0.x, g * acc[i][j][1] * iv.y + x0.y };
            float2 v1 = { g * acc[i][j][2] * iv.x + x1.x, g * acc[i][j][3] * iv.y + x1.y };
            *(float2*)&Yb[i0] = v0;
            *(float2*)&Yb[i1] = v1;
        }
    }
    #undef OLOAD
}

// ---------------------------------------------------------------------------
extern "C" void kernel_launch(void* const* d_in, const int* in_sizes, int n_in,
                              void* d_out, int out_size) {
    const float* X     = (const float*)d_in[0];
    const float* Wq    = (const float*)d_in[1];
    const float* bq    = (const float*)d_in[2];
    const float* Wk    = (const float*)d_in[3];
    const float* bk    = (const float*)d_in[4];
    const float* Wv    = (const float*)d_in[5];
    const float* bv    = (const float*)d_in[6];
    const float* gamma = (const float*)d_in[7];
    float* Y = (float*)d_out;

    __nv_bfloat16 *Xt, *Wqk, *Wvb, *Qt, *Kt, *Vb, *Eb;
    float *PS, *IV;
    cudaGetSymbolAddress((void**)&Xt,  g_Xt);
    cudaGetSymbolAddress((void**)&Wqk, g_Wqk);
    cudaGetSymbolAddress((void**)&Wvb, g_Wv);
    cudaGetSymbolAddress((void**)&Qt,  g_Qt);
    cudaGetSymbolAddress((void**)&Kt,  g_Kt);
    cudaGetSymbolAddress((void**)&Vb,  g_Vb);
    cudaGetSymbolAddress((void**)&Eb,  g_Eb);
    cudaGetSymbolAddress((void**)&PS,  g_psum);
    cudaGetSymbolAddress((void**)&IV,  g_inv);

    const int DSM = 6 * STG_BYTES;   // 61440 B
    cudaFuncSetAttribute(proj_bf16<true>,  cudaFuncAttributeMaxDynamicSharedMemorySize, DSM);
    cudaFuncSetAttribute(proj_bf16<false>, cudaFuncAttributeMaxDynamicSharedMemorySize, DSM);
    cudaFuncSetAttribute(out_bf16,         cudaFuncAttributeMaxDynamicSharedMemorySize, DSM);

    convert_x<<<dim3(NHW / 64, NC / 64, NB), 256>>>(X, Xt);
    convert_w<<<(128 * NC + NC * NC + 255) / 256, 256>>>(Wq, Wk, Wv, Wqk, Wvb);
    proj_bf16<true><<<dim3(NHW / 128, 1, NB), 256, DSM>>>(Xt, Wqk, bq, bk, 64,
                                                          nullptr, Qt, Kt);
    proj_bf16<false><<<dim3(NHW / 128, NC / 128, NB), 256, DSM>>>(Xt, Wvb, bv, bv, NC,
                                                                  Vb, nullptr, nullptr);
    scores_bf16<<<dim3(NMT, NMT, NB), 256>>>(Qt, Kt, Eb, PS);
    invsum_kernel<<<(NB * NHW + 255) / 256, 256>>>(PS, IV);
    out_bf16<<<dim3(NC / 128, NHW / 128, NB), 256, DSM>>>(Vb, Eb, IV, X, gamma, Y);
}

// round 15
// speedup vs baseline: 1.1429x; 1.0107x over previous
#include <cuda_runtime.h>
#include <cuda_bf16.h>
#include <cstdint>

// DANet spatial attention — all-bf16 mma.sync(m16n8k16), 8-warp CTAs,
// k-chunk 32, 3-stage single-sync cp.async pipeline + stream overlap:
// proj_v runs concurrently with scores/invsum. B=16, C=512, HW=2304, d=64.

#define NB 16
#define NC 512
#define NHW 2304
#define ND 64
#define NMT 18

__device__ __nv_bfloat16 g_Xt [(size_t)NB * NHW * NC];
__device__ __nv_bfloat16 g_Wqk[(size_t)128 * NC];
__device__ __nv_bfloat16 g_Wv [(size_t)NC * NC];
__device__ __nv_bfloat16 g_Qt [(size_t)NB * NHW * ND];
__device__ __nv_bfloat16 g_Kt [(size_t)NB * NHW * ND];
__device__ __nv_bfloat16 g_Vb [(size_t)NB * NC * NHW];
__device__ __nv_bfloat16 g_Eb [(size_t)NB * NHW * NHW];
__device__ float g_psum[(size_t)NB * NMT * NHW];
__device__ float g_inv [(size_t)NB * NHW];

// ---------------------------------------------------------------------------
__device__ __forceinline__ void mma_bf16(float c[4],
                                         unsigned a0, unsigned a1, unsigned a2, unsigned a3,
                                         unsigned b0, unsigned b1) {
    asm volatile(
        "mma.sync.aligned.m16n8k16.row.col.f32.bf16.bf16.f32 "
        "{%0,%1,%2,%3}, {%4,%5,%6,%7}, {%8,%9}, {%0,%1,%2,%3};"
        : "+f"(c[0]), "+f"(c[1]), "+f"(c[2]), "+f"(c[3])
        : "r"(a0), "r"(a1), "r"(a2), "r"(a3), "r"(b0), "r"(b1));
}
__device__ __forceinline__ void ldsm_x4(unsigned r[4], uint32_t addr) {
    asm volatile("ldmatrix.sync.aligned.m8n8.x4.shared.b16 {%0,%1,%2,%3}, [%4];"
        : "=r"(r[0]), "=r"(r[1]), "=r"(r[2]), "=r"(r[3]) : "r"(addr));
}
#define CPA16(dst, src) asm volatile("cp.async.ca.shared.global [%0], [%1], 16;\n" :: "r"(dst), "l"(src))
#define CP_COMMIT()     asm volatile("cp.async.commit_group;\n")
#define CP_WAIT1()      asm volatile("cp.async.wait_group 1;\n")
#define CP_WAIT0()      asm volatile("cp.async.wait_group 0;\n")

#define SB32 40
#define SB64 72
#define TILE32 (128 * SB32)
#define STG_BYTES (TILE32 * 2)       // 10240 B

// ---------------------------------------------------------------------------
// X [b][c][n] fp32 -> Xt [b][n][c] bf16.  64x64 tiles, float4 I/O.
// ---------------------------------------------------------------------------
__global__ void __launch_bounds__(256)
convert_x(const float* __restrict__ X, __nv_bfloat16* __restrict__ Xt) {
    __shared__ float t[64][65];
    const int b  = blockIdx.z;
    const int n0 = blockIdx.x * 64;
    const int c0 = blockIdx.y * 64;
    const int tx = threadIdx.x & 15, ty = threadIdx.x >> 4;
    const float* Xb = X + (size_t)b * NC * NHW;
    __nv_bfloat16* Tb = Xt + (size_t)b * NHW * NC;

    #pragma unroll
    for (int k = 0; k < 4; k++) {
        int row = ty + k * 16;
        float4 v = *(const float4*)&Xb[(size_t)(c0 + row) * NHW + n0 + tx * 4];
        t[row][tx * 4 + 0] = v.x;
        t[row][tx * 4 + 1] = v.y;
        t[row][tx * 4 + 2] = v.z;
        t[row][tx * 4 + 3] = v.w;
    }
    __syncthreads();
    #pragma unroll
    for (int k = 0; k < 4; k++) {
        int nrow = ty + k * 16;
        float v0 = t[tx * 4 + 0][nrow];
        float v1 = t[tx * 4 + 1][nrow];
        float v2 = t[tx * 4 + 2][nrow];
        float v3 = t[tx * 4 + 3][nrow];
        __nv_bfloat162 h0 = __floats2bfloat162_rn(v0, v1);
        __nv_bfloat162 h1 = __floats2bfloat162_rn(v2, v3);
        __nv_bfloat162* dst = (__nv_bfloat162*)&Tb[(size_t)(n0 + nrow) * NC + c0 + tx * 4];
        dst[0] = h0;
        dst[1] = h1;
    }
}

__global__ void __launch_bounds__(256)
convert_w(const float* __restrict__ Wq, const float* __restrict__ Wk,
          const float* __restrict__ Wv,
          __nv_bfloat16* __restrict__ Wqk, __nv_bfloat16* __restrict__ Wvb) {
    int idx = blockIdx.x * 256 + threadIdx.x;
    const int NQK = 128 * NC;
    if (idx < NQK) {
        int row = idx >> 9, col = idx & 511;
        float v = (row < 64) ? Wq[row * NC + col] : Wk[(row - 64) * NC + col];
        Wqk[idx] = __float2bfloat16(v);
    }
    int j = idx - NQK;
    if (j >= 0 && j < NC * NC)
        Wvb[j] = __float2bfloat16(Wv[j]);
}

// ---------------------------------------------------------------------------
// bf16 projection, 256 thr, 8 warps (2x4), warp tile 64x32, k-chunk 32,
// 3-stage single-sync pipeline.
// ---------------------------------------------------------------------------
template<bool QKT>
__global__ void __launch_bounds__(256, 2)
proj_bf16(const __nv_bfloat16* __restrict__ Xt, const __nv_bfloat16* __restrict__ W,
          const float* __restrict__ B1, const float* __restrict__ B2, int split,
          __nv_bfloat16* __restrict__ Pv,
          __nv_bfloat16* __restrict__ Qt, __nv_bfloat16* __restrict__ Kt) {
    extern __shared__ __align__(16) __nv_bfloat16 dsm[];
    __nv_bfloat16* sW = dsm;
    __nv_bfloat16* sX = dsm + 3 * TILE32;

    const int b  = blockIdx.z;
    const int n0 = blockIdx.x * 128;
    const int o0 = blockIdx.y * 128;
    const __nv_bfloat16* Xb = Xt + (size_t)b * NHW * NC;

    const int tid = threadIdx.x;
    const int lane = tid & 31, wid = tid >> 5;
    const int wm = (wid >> 2) * 64, wn = (wid & 3) * 32;
    const int lr = lane >> 2, lc = lane & 3;
    const int lt = lane >> 3, l8 = lane & 7;
    const int aro = ((lt & 1) << 3) + l8, ako = (lt >> 1) << 3;
    const int bro = ((lt >> 1) << 3) + l8, bko = (lt & 1) << 3;

    const unsigned sWu = (unsigned)__cvta_generic_to_shared(sW);
    const unsigned sXu = (unsigned)__cvta_generic_to_shared(sX);

    const int lrow = tid >> 1, lc8 = (tid & 1) * 2;

    float acc[4][4][4];
    #pragma unroll
    for (int i = 0; i < 4; i++)
        #pragma unroll
        for (int j = 0; j < 4; j++)
            #pragma unroll
            for (int q = 0; q < 4; q++) acc[i][j][q] = 0.f;

    const int NCH = NC / 32;   // 16
    #define PLOAD(ch, stg) {                                                          \
        int mm = (ch) * 32;                                                           \
        _Pragma("unroll")                                                             \
        for (int p = 0; p < 2; p++) {                                                 \
            CPA16(sWu + ((stg) * TILE32 + lrow * SB32 + (lc8 + p) * 8) * 2,           \
                  W  + (size_t)(o0 + lrow) * NC + mm + (lc8 + p) * 8);                \
            CPA16(sXu + ((stg) * TILE32 + lrow * SB32 + (lc8 + p) * 8) * 2,           \
                  Xb + (size_t)(n0 + lrow) * NC + mm + (lc8 + p) * 8);                \
        }                                                                             \
        CP_COMMIT();                                                                  \
    }

    PLOAD(0, 0); PLOAD(1, 1);
    #pragma unroll 1
    for (int ch = 0; ch < NCH; ch++) {
        int stg = ch % 3;
        if (ch + 1 < NCH) { CP_WAIT1(); } else { CP_WAIT0(); }
        __syncthreads();
        if (ch + 2 < NCH) PLOAD(ch + 2, (ch + 2) % 3);
        unsigned aB = sWu + (unsigned)(stg * TILE32) * 2;
        unsigned bB = sXu + (unsigned)(stg * TILE32) * 2;
        #pragma unroll
        for (int ks = 0; ks < 2; ks++) {
            const int kb = ks * 16;
            unsigned a[4][4], rb[2][4];
            #pragma unroll
            for (int i = 0; i < 4; i++)
                ldsm_x4(a[i], aB + ((wm + i * 16 + aro) * SB32 + kb + ako) * 2);
            #pragma unroll
            for (int j = 0; j < 2; j++)
                ldsm_x4(rb[j], bB + ((wn + j * 16 + bro) * SB32 + kb + bko) * 2);
            #pragma unroll
            for (int i = 0; i < 4; i++)
                #pragma unroll
                for (int j = 0; j < 4; j++)
                    mma_bf16(acc[i][j], a[i][0], a[i][1], a[i][2], a[i][3],
                             rb[j >> 1][(j & 1) * 2], rb[j >> 1][(j & 1) * 2 + 1]);
        }
    }

    if (QKT) {
        __nv_bfloat16* Qb = Qt + (size_t)b * NHW * ND;
        __nv_bfloat16* Kb = Kt + (size_t)b * NHW * ND;
        #pragma unroll
        for (int i = 0; i < 4; i++) {
            int r0 = o0 + wm + i * 16 + lr;
            int r1 = r0 + 8;
            float bo0 = (r0 < split ? B1[r0] : B2[r0 - split]);
            float bo1 = (r1 < split ? B1[r1] : B2[r1 - split]);
            __nv_bfloat16* P0 = (r0 < split ? Qb : Kb);
            __nv_bfloat16* P1 = (r1 < split ? Qb : Kb);
            int rr0 = (r0 < split ? r0 : r0 - split);
            int rr1 = (r1 < split ? r1 : r1 - split);
            #pragma unroll
            for (int j = 0; j < 4; j++) {
                int col = n0 + wn + j * 8 + lc * 2;
                P0[(size_t)col * ND + rr0]       = __float2bfloat16(acc[i][j][0] + bo0);
                P0[(size_t)(col + 1) * ND + rr0] = __float2bfloat16(acc[i][j][1] + bo0);
                P1[(size_t)col * ND + rr1]       = __float2bfloat16(acc[i][j][2] + bo1);
                P1[(size_t)(col + 1) * ND + rr1] = __float2bfloat16(acc[i][j][3] + bo1);
            }
        }
    } else {
        __nv_bfloat16* Pb = Pv + (size_t)b * NC * NHW;
        #pragma unroll
        for (int i = 0; i < 4; i++) {
            int r0 = o0 + wm + i * 16 + lr;
            int r1 = r0 + 8;
            float bo0 = B1[r0];
            float bo1 = B1[r1];
            #pragma unroll
            for (int j = 0; j < 4; j++) {
                int col = n0 + wn + j * 8 + lc * 2;
                __nv_bfloat162 v0 = __floats2bfloat162_rn(acc[i][j][0] + bo0, acc[i][j][1] + bo0);
                __nv_bfloat162 v1 = __floats2bfloat162_rn(acc[i][j][2] + bo1, acc[i][j][3] + bo1);
                *(__nv_bfloat162*)&Pb[(size_t)r0 * NHW + col] = v0;
                *(__nv_bfloat162*)&Pb[(size_t)r1 * NHW + col] = v1;
            }
        }
    }
    #undef PLOAD
}

// ---------------------------------------------------------------------------
// Scores+exp, 256 thr, 8 warps (2x4), warp tile 64x32, single k=64 pass.
// ---------------------------------------------------------------------------
__global__ void __launch_bounds__(256, 2)
scores_bf16(const __nv_bfloat16* __restrict__ Qt, const __nv_bfloat16* __restrict__ Kt,
            __nv_bfloat16* __restrict__ E, float* __restrict__ psum) {
    const int b  = blockIdx.z;
    const int mt = blockIdx.x;
    const int m0 = mt * 128;
    const int n0 = blockIdx.y * 128;
    const __nv_bfloat16* Qb = Qt + (size_t)b * NHW * ND;
    const __nv_bfloat16* Kb = Kt + (size_t)b * NHW * ND;
    __nv_bfloat16*       Eb = E + (size_t)b * NHW * NHW;

    __shared__ __align__(16) __nv_bfloat16 sQ[128 * SB64];
    __shared__ __align__(16) __nv_bfloat16 sK[128 * SB64];
    __shared__ float sred[4][128];

    const int tid = threadIdx.x;
    const int lane = tid & 31, wid = tid >> 5;
    const int wm = (wid >> 2) * 64, wn = (wid & 3) * 32;
    const int lr = lane >> 2, lc = lane & 3;
    const int lt = lane >> 3, l8 = lane & 7;
    const int aro = ((lt & 1) << 3) + l8, ako = (lt >> 1) << 3;
    const int bro = ((lt >> 1) << 3) + l8, bko = (lt & 1) << 3;

    const unsigned sQu = (unsigned)__cvta_generic_to_shared(&sQ[0]);
    const unsigned sKu = (unsigned)__cvta_generic_to_shared(&sK[0]);

    #pragma unroll
    for (int p = 0; p < 4; p++) {
        int idx = tid + p * 256;
        int row = idx >> 3, c = idx & 7;
        CPA16(sQu + (row * SB64 + c * 8) * 2, Qb + (size_t)(n0 + row) * ND + c * 8);
        CPA16(sKu + (row * SB64 + c * 8) * 2, Kb + (size_t)(m0 + row) * ND + c * 8);
    }
    CP_COMMIT();

    float acc[4][4][4];
    #pragma unroll
    for (int i = 0; i < 4; i++)
        #pragma unroll
        for (int j = 0; j < 4; j++)
            #pragma unroll
            for (int q = 0; q < 4; q++) acc[i][j][q] = 0.f;

    CP_WAIT0();
    __syncthreads();

    #pragma unroll
    for (int t4 = 0; t4 < 4; t4++) {
        const int kb = t4 * 16;
        unsigned a[4][4], rb[2][4];
        #pragma unroll
        for (int i = 0; i < 4; i++)
            ldsm_x4(a[i], sQu + ((wm + i * 16 + aro) * SB64 + kb + ako) * 2);
        #pragma unroll
        for (int j = 0; j < 2; j++)
            ldsm_x4(rb[j], sKu + ((wn + j * 16 + bro) * SB64 + kb + bko) * 2);
        #pragma unroll
        for (int i = 0; i < 4; i++)
            #pragma unroll
            for (int j = 0; j < 4; j++)
                mma_bf16(acc[i][j], a[i][0], a[i][1], a[i][2], a[i][3],
                         rb[j >> 1][(j & 1) * 2], rb[j >> 1][(j & 1) * 2 + 1]);
    }

    const int cw = wid & 3;
    #pragma unroll
    for (int i = 0; i < 4; i++) {
        int r0 = n0 + wm + i * 16 + lr;
        int r1 = r0 + 8;
        float s0 = 0.f, s1 = 0.f;
        #pragma unroll
        for (int j = 0; j < 4; j++) {
            int col = m0 + wn + j * 8 + lc * 2;
            __nv_bfloat162 h0 = __floats2bfloat162_rn(__expf(acc[i][j][0]), __expf(acc[i][j][1]));
            __nv_bfloat162 h1 = __floats2bfloat162_rn(__expf(acc[i][j][2]), __expf(acc[i][j][3]));
            *(__nv_bfloat162*)&Eb[(size_t)r0 * NHW + col] = h0;
            *(__nv_bfloat162*)&Eb[(size_t)r1 * NHW + col] = h1;
            float2 f0 = __bfloat1622float2(h0);
            float2 f1 = __bfloat1622float2(h1);
            s0 += f0.x + f0.y;
            s1 += f1.x + f1.y;
        }
        s0 += __shfl_xor_sync(0xffffffffu, s0, 1);
        s0 += __shfl_xor_sync(0xffffffffu, s0, 2);
        s1 += __shfl_xor_sync(0xffffffffu, s1, 1);
        s1 += __shfl_xor_sync(0xffffffffu, s1, 2);
        if (lc == 0) {
            sred[cw][wm + i * 16 + lr]     = s0;
            sred[cw][wm + i * 16 + lr + 8] = s1;
        }
    }
    __syncthreads();
    if (tid < 128) {
        float s = sred[0][tid] + sred[1][tid] + sred[2][tid] + sred[3][tid];
        psum[((size_t)(b * NMT + mt)) * NHW + n0 + tid] = s;
    }
}

// ---------------------------------------------------------------------------
__global__ void invsum_kernel(const float* __restrict__ psum, float* __restrict__ inv) {
    int idx = blockIdx.x * 256 + threadIdx.x;
    if (idx >= NB * NHW) return;
    int b = idx / NHW, n = idx - b * NHW;
    const float* ps = psum + (size_t)b * NMT * NHW + n;
    float s = 0.f;
    #pragma unroll
    for (int mt = 0; mt < NMT; mt++) s += ps[(size_t)mt * NHW];
    inv[idx] = 1.f / s;
}

// ---------------------------------------------------------------------------
// Out, 256 thr, 8 warps (2x4), warp tile 64x32, k-chunk 32, 3-stage
// single-sync pipeline, NCH=72.
// ---------------------------------------------------------------------------
__global__ void __launch_bounds__(256, 2)
out_bf16(const __nv_bfloat16* __restrict__ V, const __nv_bfloat16* __restrict__ E,
         const float* __restrict__ inv, const float* __restrict__ X,
         const float* __restrict__ gamma, float* __restrict__ Y) {
    extern __shared__ __align__(16) __nv_bfloat16 dsm[];
    __nv_bfloat16* sV = dsm;
    __nv_bfloat16* sE = dsm + 3 * TILE32;

    const int b  = blockIdx.z;
    const int c0 = blockIdx.x * 128;
    const int n0 = blockIdx.y * 128;
    const __nv_bfloat16* Vb = V + (size_t)b * NC * NHW;
    const __nv_bfloat16* Ab = E + (size_t)b * NHW * NHW;
    const float* Xb = X + (size_t)b * NC * NHW;
    const float* invb = inv + (size_t)b * NHW;
    float*       Yb = Y + (size_t)b * NC * NHW;

    const int tid = threadIdx.x;
    const int lane = tid & 31, wid = tid >> 5;
    const int wm = (wid >> 2) * 64, wn = (wid & 3) * 32;
    const int lr = lane >> 2, lc = lane & 3;
    const int lt = lane >> 3, l8 = lane & 7;
    const int aro = ((lt & 1) << 3) + l8, ako = (lt >> 1) << 3;
    const int bro = ((lt >> 1) << 3) + l8, bko = (lt & 1) << 3;

    const unsigned sVu = (unsigned)__cvta_generic_to_shared(sV);
    const unsigned sEu = (unsigned)__cvta_generic_to_shared(sE);

    const int lrow = tid >> 1, lc8 = (tid & 1) * 2;

    float acc[4][4][4];
    #pragma unroll
    for (int i = 0; i < 4; i++)
        #pragma unroll
        for (int j = 0; j < 4; j++)
            #pragma unroll
            for (int q = 0; q < 4; q++) acc[i][j][q] = 0.f;

    const int NCH = NHW / 32;   // 72
    #define OLOAD(ch, stg) {                                                          \
        int mm = (ch) * 32;                                                           \
        _Pragma("unroll")                                                             \
        for (int p = 0; p < 2; p++) {                                                 \
            CPA16(sVu + ((stg) * TILE32 + lrow * SB32 + (lc8 + p) * 8) * 2,           \
                  Vb + (size_t)(c0 + lrow) * NHW + mm + (lc8 + p) * 8);               \
            CPA16(sEu + ((stg) * TILE32 + lrow * SB32 + (lc8 + p) * 8) * 2,           \
                  Ab + (size_t)(n0 + lrow) * NHW + mm + (lc8 + p) * 8);               \
        }                                                                             \
        CP_COMMIT();                                                                  \
    }

    OLOAD(0, 0); OLOAD(1, 1);
    #pragma unroll 1
    for (int ch = 0; ch < NCH; ch++) {
        int stg = ch % 3;
        if (ch + 1 < NCH) { CP_WAIT1(); } else { CP_WAIT0(); }
        __syncthreads();
        if (ch + 2 < NCH) OLOAD(ch + 2, (ch + 2) % 3);
        unsigned aB = sVu + (unsigned)(stg * TILE32) * 2;
        unsigned bB = sEu + (unsigned)(stg * TILE32) * 2;
        #pragma unroll
        for (int ks = 0; ks < 2; ks++) {
            const int kb = ks * 16;
            unsigned a[4][4], rb[2][4];
            #pragma unroll
            for (int i = 0; i < 4; i++)
                ldsm_x4(a[i], aB + ((wm + i * 16 + aro) * SB32 + kb + ako) * 2);
            #pragma unroll
            for (int j = 0; j < 2; j++)
                ldsm_x4(rb[j], bB + ((wn + j * 16 + bro) * SB32 + kb + bko) * 2);
            #pragma unroll
            for (int i = 0; i < 4; i++)
                #pragma unroll
                for (int j = 0; j < 4; j++)
                    mma_bf16(acc[i][j], a[i][0], a[i][1], a[i][2], a[i][3],
                             rb[j >> 1][(j & 1) * 2], rb[j >> 1][(j & 1) * 2 + 1]);
        }
    }

    const float g = gamma[0];
    #pragma unroll
    for (int i = 0; i < 4; i++) {
        int r0 = c0 + wm + i * 16 + lr;
        int r1 = r0 + 8;
        #pragma unroll
        for (int j = 0; j < 4; j++) {
            int col = n0 + wn + j * 8 + lc * 2;
            float2 iv = *(const float2*)&invb[col];
            size_t i0 = (size_t)r0 * NHW + col;
            size_t i1 = (size_t)r1 * NHW + col;
            float2 x0 = *(const float2*)&Xb[i0];
            float2 x1 = *(const float2*)&Xb[i1];
            float2 v0 = { g * acc[i][j][0] * iv.x + x0.x, g * acc[i][j][1] * iv.y + x0.y };
            float2 v1 = { g * acc[i][j][2] * iv.x + x1.x, g * acc[i][j][3] * iv.y + x1.y };
            *(float2*)&Yb[i0] = v0;
            *(float2*)&Yb[i1] = v1;
        }
    }
    #undef OLOAD
}

// ---------------------------------------------------------------------------
static cudaStream_t side_stream() {
    static cudaStream_t s = nullptr;
    if (!s) cudaStreamCreateWithFlags(&s, cudaStreamNonBlocking);
    return s;
}
static cudaEvent_t fork_event() {
    static cudaEvent_t e = nullptr;
    if (!e) cudaEventCreateWithFlags(&e, cudaEventDisableTiming);
    return e;
}
static cudaEvent_t join_event() {
    static cudaEvent_t e = nullptr;
    if (!e) cudaEventCreateWithFlags(&e, cudaEventDisableTiming);
    return e;
}

extern "C" void kernel_launch(void* const* d_in, const int* in_sizes, int n_in,
                              void* d_out, int out_size) {
    const float* X     = (const float*)d_in[0];
    const float* Wq    = (const float*)d_in[1];
    const float* bq    = (const float*)d_in[2];
    const float* Wk    = (const float*)d_in[3];
    const float* bk    = (const float*)d_in[4];
    const float* Wv    = (const float*)d_in[5];
    const float* bv    = (const float*)d_in[6];
    const float* gamma = (const float*)d_in[7];
    float* Y = (float*)d_out;

    __nv_bfloat16 *Xt, *Wqk, *Wvb, *Qt, *Kt, *Vb, *Eb;
    float *PS, *IV;
    cudaGetSymbolAddress((void**)&Xt,  g_Xt);
    cudaGetSymbolAddress((void**)&Wqk, g_Wqk);
    cudaGetSymbolAddress((void**)&Wvb, g_Wv);
    cudaGetSymbolAddress((void**)&Qt,  g_Qt);
    cudaGetSymbolAddress((void**)&Kt,  g_Kt);
    cudaGetSymbolAddress((void**)&Vb,  g_Vb);
    cudaGetSymbolAddress((void**)&Eb,  g_Eb);
    cudaGetSymbolAddress((void**)&PS,  g_psum);
    cudaGetSymbolAddress((void**)&IV,  g_inv);

    const int DSM = 6 * STG_BYTES;   // 61440 B
    cudaFuncSetAttribute(proj_bf16<true>,  cudaFuncAttributeMaxDynamicSharedMemorySize, DSM);
    cudaFuncSetAttribute(proj_bf16<false>, cudaFuncAttributeMaxDynamicSharedMemorySize, DSM);
    cudaFuncSetAttribute(out_bf16,         cudaFuncAttributeMaxDynamicSharedMemorySize, DSM);

    cudaStream_t s2 = side_stream();
    cudaEvent_t evF = fork_event();
    cudaEvent_t evJ = join_event();

    // main stream: converts + QK projection
    convert_x<<<dim3(NHW / 64, NC / 64, NB), 256>>>(X, Xt);
    convert_w<<<(128 * NC + NC * NC + 255) / 256, 256>>>(Wq, Wk, Wv, Wqk, Wvb);
    proj_bf16<true><<<dim3(NHW / 128, 1, NB), 256, DSM>>>(Xt, Wqk, bq, bk, 64,
                                                          nullptr, Qt, Kt);
    // fork: proj_v on side stream, concurrent with scores/invsum on main
    cudaEventRecord(evF, 0);
    cudaStreamWaitEvent(s2, evF, 0);
    proj_bf16<false><<<dim3(NHW / 128, NC / 128, NB), 256, DSM, s2>>>(
        Xt, Wvb, bv, bv, NC, Vb, nullptr, nullptr);

    scores_bf16<<<dim3(NMT, NMT, NB), 256>>>(Qt, Kt, Eb, PS);
    invsum_kernel<<<(NB * NHW + 255) / 256, 256>>>(PS, IV);

    // join: out needs both proj_v (s2) and invsum (main)
    cudaEventRecord(evJ, s2);
    cudaStreamWaitEvent(0, evJ, 0);
    out_bf16<<<dim3(NC / 128, NHW / 128, NB), 256, DSM>>>(Vb, Eb, IV, X, gamma, Y);
}